// round 2
// baseline (speedup 1.0000x reference)
#include <cuda_runtime.h>

// out[row, t] = x[row, t - s]  if 0 <= t - s < T else 0
// rows = 256, T = 160000 (T % 4 == 0), s = shifts[row] - max_shift in [-16000, 16000]
//
// Strategy: all global reads and writes are aligned float4 (LDG.128/STG.128).
// The per-row misalignment a = (t - s) mod 4 is uniform across the block, so
// each thread loads ONE aligned source word; the neighbor word comes from
// lane+1 via warp shuffle (lane 31 loads its neighbor itself). Out-of-range
// words are zero-filled, which exactly reproduces the reference's zero padding
// because every aligned word is entirely inside or outside [0, T).

__global__ void random_shift_kernel(const float4* __restrict__ x4,
                                    const int* __restrict__ shifts,
                                    float4* __restrict__ out4,
                                    int T4, int max_shift) {
    const int row = blockIdx.y;
    const int s = shifts[row] - max_shift;

    const int tid = blockIdx.x * blockDim.x + threadIdx.x;   // output word index
    const bool active = tid < T4;

    // source element range for this output word: [u, u+4), u = 4*tid - s
    const int u = 4 * tid - s;
    const int a = ((u % 4) + 4) % 4;        // intra-word offset, uniform per row
    const int w = (u - a) >> 2;             // aligned source word index (floor)

    const size_t base = (size_t)row * (size_t)T4;

    float4 lo = make_float4(0.f, 0.f, 0.f, 0.f);
    if (w >= 0 && w < T4)
        lo = __ldg(x4 + base + w);

    // hi = lane (l+1)'s lo; lane 31 loads its own neighbor word
    float4 hi;
    hi.x = __shfl_down_sync(0xFFFFFFFFu, lo.x, 1);
    hi.y = __shfl_down_sync(0xFFFFFFFFu, lo.y, 1);
    hi.z = __shfl_down_sync(0xFFFFFFFFu, lo.z, 1);
    hi.w = __shfl_down_sync(0xFFFFFFFFu, lo.w, 1);
    if ((threadIdx.x & 31) == 31) {
        const int w1 = w + 1;
        hi = make_float4(0.f, 0.f, 0.f, 0.f);
        if (w1 >= 0 && w1 < T4)
            hi = __ldg(x4 + base + w1);
    }

    float4 v;
    switch (a) {                             // uniform per block: no divergence
    case 0:  v = lo; break;
    case 1:  v = make_float4(lo.y, lo.z, lo.w, hi.x); break;
    case 2:  v = make_float4(lo.z, lo.w, hi.x, hi.y); break;
    default: v = make_float4(lo.w, hi.x, hi.y, hi.z); break;
    }

    if (active)
        out4[base + tid] = v;
}

extern "C" void kernel_launch(void* const* d_in, const int* in_sizes, int n_in,
                              void* d_out, int out_size) {
    const float4* x4     = (const float4*)d_in[0];
    const int*    shifts = (const int*)d_in[1];
    float4*       out4   = (float4*)d_out;

    const int rows = in_sizes[1];            // B*M = 256
    const int T    = in_sizes[0] / rows;     // 160000
    const int T4   = T / 4;                  // 40000
    const int max_shift = T / 10;            // 16000

    const int threads = 256;
    dim3 grid((T4 + threads - 1) / threads, rows);
    random_shift_kernel<<<grid, threads>>>(x4, shifts, out4, T4, max_shift);
}

// round 3
// speedup vs baseline: 1.0786x; 1.0786x over previous
#include <cuda_runtime.h>

// out[row, t] = x[row, t - s]  if 0 <= t - s < T else 0
// rows = 256, T = 160000 (T % 4 == 0), s = shifts[row] - max_shift in [-16000, 16000]
//
// Each block owns a contiguous tile of WPB float4-words of one row. Each thread
// handles VEC=4 words strided by blockDim (every load/store instruction fully
// coalesced). All loads are issued before any store (MLP=4 float4-equivalents
// per thread). Streaming cache hints (__ldcs/__stcs) since there is zero reuse.
// Interior tiles (~90%) skip all bounds predication.

#define VEC 4
#define THREADS 256
#define WPB (VEC * THREADS)   // 1024 float4 words = 4096 floats per tile

__global__ void __launch_bounds__(THREADS)
random_shift_kernel(const float* __restrict__ x,
                    const int* __restrict__ shifts,
                    float4* __restrict__ out4,
                    int T, int max_shift) {
    const int row = blockIdx.y;
    const int s = shifts[row] - max_shift;

    const int T4 = T >> 2;
    const int tile0 = blockIdx.x * WPB;                    // first word of tile
    const size_t ebase = (size_t)row * (size_t)T;          // element base
    const size_t wbase = (size_t)row * (size_t)T4;         // word base
    const float* __restrict__ xr = x + ebase;

    // tile source element range: [4*tile0 - s, 4*(tile0+WPB) - s)
    const int src_lo = 4 * tile0 - s;
    const int src_hi = 4 * (tile0 + WPB) - s;
    const bool interior = (src_lo >= 0) && (src_hi <= T) && (tile0 + WPB <= T4);

    float4 v[VEC];

    if (interior) {
#pragma unroll
        for (int k = 0; k < VEC; ++k) {
            const int w = tile0 + threadIdx.x + k * THREADS;
            const int u = 4 * w - s;
            v[k].x = __ldcs(xr + u);
            v[k].y = __ldcs(xr + u + 1);
            v[k].z = __ldcs(xr + u + 2);
            v[k].w = __ldcs(xr + u + 3);
        }
#pragma unroll
        for (int k = 0; k < VEC; ++k) {
            const int w = tile0 + threadIdx.x + k * THREADS;
            __stcs(out4 + wbase + w, v[k]);
        }
    } else {
#pragma unroll
        for (int k = 0; k < VEC; ++k) {
            const int w = tile0 + threadIdx.x + k * THREADS;
            const int u = 4 * w - s;
            float t0 = 0.f, t1 = 0.f, t2 = 0.f, t3 = 0.f;
            if (w < T4) {
                if (u >= 0 && u + 3 < T) {
                    t0 = __ldcs(xr + u);
                    t1 = __ldcs(xr + u + 1);
                    t2 = __ldcs(xr + u + 2);
                    t3 = __ldcs(xr + u + 3);
                } else {
                    if (u >= 0     && u < T)     t0 = __ldcs(xr + u);
                    if (u + 1 >= 0 && u + 1 < T) t1 = __ldcs(xr + u + 1);
                    if (u + 2 >= 0 && u + 2 < T) t2 = __ldcs(xr + u + 2);
                    if (u + 3 >= 0 && u + 3 < T) t3 = __ldcs(xr + u + 3);
                }
            }
            v[k] = make_float4(t0, t1, t2, t3);
        }
#pragma unroll
        for (int k = 0; k < VEC; ++k) {
            const int w = tile0 + threadIdx.x + k * THREADS;
            if (w < T4)
                __stcs(out4 + wbase + w, v[k]);
        }
    }
}

extern "C" void kernel_launch(void* const* d_in, const int* in_sizes, int n_in,
                              void* d_out, int out_size) {
    const float* x      = (const float*)d_in[0];
    const int*   shifts = (const int*)d_in[1];
    float4*      out4   = (float4*)d_out;

    const int rows = in_sizes[1];            // B*M = 256
    const int T    = in_sizes[0] / rows;     // 160000
    const int T4   = T / 4;                  // 40000
    const int max_shift = T / 10;            // 16000

    dim3 grid((T4 + WPB - 1) / WPB, rows);   // (40, 256)
    random_shift_kernel<<<grid, THREADS>>>(x, shifts, out4, T, max_shift);
}